// round 7
// baseline (speedup 1.0000x reference)
#include <cuda_runtime.h>

#define BATCH 8
#define MODES 16
#define NPH   8
#define NST   12870
#define OUTD  128
#define NDEL  128          // Glynn: 2^(n-1) terms
#define CS2   16           // delta-chunk in table kernel
#define KC    16           // K stage depth in class GEMM
#define NTILE 23
#define PW    416          // padded table width (sum of 32-aligned class widths)
#define PW4   (PW / 2)     // float4 row stride

__constant__ int c_NJ[9]   = {1, 8, 28, 56, 70, 56, 28, 8, 1};
__constant__ int c_POFF[9] = {0, 32, 64, 96, 160, 256, 320, 352, 384};
__constant__ int c_OFF2[9] = {0, 1, 65, 849, 3985, 8885, 12021, 12805, 12869};
// tiles: {j, a0, b0} — all 32x32, uniform cost
__constant__ int c_TJ[NTILE]  = {4,4,4,4,4,4,4,4,4, 3,3,3,3, 5,5,5,5, 2,6,1,7,0,8};
__constant__ int c_TA[NTILE]  = {0,0,0,32,32,32,64,64,64, 0,0,32,32, 0,0,32,32, 0,0,0,0,0,0};
__constant__ int c_TB[NTILE]  = {0,32,64,0,32,64,0,32,64, 0,32,0,32, 0,32,0,32, 0,0,0,0,0,0};

// ---------------- device scratch ----------------
__device__ __align__(16) float2 g_PT[BATCH][2][NDEL][PW];   // 6.8MB padded tables
__device__ int    g_invmap[NST];
__device__ float  g_praw[BATCH][NST];
__device__ float  g_sum[BATCH];

// ============ kernel 1: fused setup + class-map + Glynn tables + out=bias ====
// grid: (NDEL/CS2=8, side=2, batch=8), 256 threads
__global__ __launch_bounds__(256) void k_tables(const float* __restrict__ x,
                                                const float* __restrict__ th1,
                                                const float* __restrict__ th2,
                                                const float* __restrict__ mr,
                                                const float* __restrict__ mi,
                                                const int* __restrict__ rows,
                                                const float* __restrict__ bias,
                                                float* __restrict__ out) {
    __shared__ float2 e1[16], e2[16], ex[16];
    __shared__ float2 A[16][16], Bm[16][16];
    __shared__ float2 uin[8][8];
    __shared__ float2 vs[CS2][8];
    __shared__ float2 P[256][CS2 + 1];
    __shared__ int posmap[PW];    // padded position -> mask (or -1)
    __shared__ int s_rank[256];

    int t = threadIdx.x;
    int d0 = blockIdx.x * CS2;
    int side = blockIdx.y, b = blockIdx.z;

    if (t < 16) {
        float s, c;
        sincosf(th1[t], &s, &c); e1[t] = make_float2(c, s);
        sincosf(th2[t], &s, &c); e2[t] = make_float2(c, s);
        sincosf(x[b * 16 + t], &s, &c); ex[t] = make_float2(c, s);
    }
    // init posmap
    for (int q = t; q < PW; q += 256) posmap[q] = -1;
    __syncthreads();
    // rank within popc class
    {
        int c = t, pc = __popc(c), r = 0;
        for (int cp = 0; cp < c; cp++) r += (__popc(cp) == pc) ? 1 : 0;
        s_rank[c] = r;
        posmap[c_POFF[pc] + r] = c;
    }
    __syncthreads();
    // A = M1 diag(e1) M0 ; B = M3 diag(e2) M2
    {
        int i = t >> 4, j = t & 15;
        float ar = 0, ai = 0, br = 0, bi = 0;
        for (int m = 0; m < 16; m++) {
            float m1r = mr[256 + i * 16 + m], m1i = mi[256 + i * 16 + m];
            float m0r = mr[m * 16 + j],       m0i = mi[m * 16 + j];
            float tr = e1[m].x * m0r - e1[m].y * m0i;
            float ti = e1[m].x * m0i + e1[m].y * m0r;
            ar += m1r * tr - m1i * ti;
            ai += m1r * ti + m1i * tr;
            float m3r = mr[3 * 256 + i * 16 + m], m3i = mi[3 * 256 + i * 16 + m];
            float m2r = mr[2 * 256 + m * 16 + j], m2i = mi[2 * 256 + m * 16 + j];
            float ur = e2[m].x * m2r - e2[m].y * m2i;
            float ui = e2[m].x * m2i + e2[m].y * m2r;
            br += m3r * ur - m3i * ui;
            bi += m3r * ui + m3i * ur;
        }
        A[i][j]  = make_float2(ar, ai);
        Bm[i][j] = make_float2(br, bi);
    }
    __syncthreads();
    // Uin rows for this side
    if (t < 64) {
        int r = t >> 3, n = t & 7, p = side * 8 + r;
        float ur = 0, ui = 0;
        for (int m = 0; m < 16; m++) {
            float tr = ex[m].x * A[m][n].x - ex[m].y * A[m][n].y;
            float ti = ex[m].x * A[m][n].y + ex[m].y * A[m][n].x;
            ur += Bm[p][m].x * tr - Bm[p][m].y * ti;
            ui += Bm[p][m].x * ti + Bm[p][m].y * tr;
        }
        uin[r][n] = make_float2(ur, ui);
    }
    __syncthreads();
    // Glynn row sums
    if (t < CS2 * 8) {
        int sl = t >> 3, r = t & 7, d = d0 + sl;
        float vr = uin[r][0].x, vi = uin[r][0].y;
        for (int k = 1; k < 8; k++) {
            if ((d >> (k - 1)) & 1) { vr -= uin[r][k].x; vi -= uin[r][k].y; }
            else                    { vr += uin[r][k].x; vi += uin[r][k].y; }
        }
        vs[sl][r] = make_float2(vr, vi);
    }
    if (t < CS2) P[0][t] = make_float2(1.f, 0.f);
    __syncthreads();
    // subset-product DP
    for (int r = 0; r < 8; r++) {
        int cnt = (1 << r) * CS2;
        for (int idx = t; idx < cnt; idx += 256) {
            int cprev = idx >> 4, sl = idx & 15;
            float2 p = P[cprev][sl], v = vs[sl][r];
            P[cprev | (1 << r)][sl] =
                make_float2(p.x * v.x - p.y * v.y, p.x * v.y + p.y * v.x);
        }
        __syncthreads();
    }
    // write padded table; fold Glynn sign + 2^-7 into high side; zero padding
    for (int sl = 0; sl < CS2; sl++) {
        int d = d0 + sl;
        float f = 1.f;
        if (side == 1) f = ((__popc(d) & 1) ? -0.0078125f : 0.0078125f);
        for (int pos = t; pos < PW; pos += 256) {
            int mask = posmap[pos];
            float2 p = make_float2(0.f, 0.f);
            if (mask >= 0) { p = P[mask][sl]; p.x *= f; p.y *= f; }
            g_PT[b][side][d][pos] = p;
        }
    }
    // inverse state map (side-0 blocks: 64 blocks x 256 = 16384 >= NST)
    if (side == 0) {
        int gid = (blockIdx.x + 8 * blockIdx.z) * 256 + t;
        if (gid < NST) {
            int cl = 0, ch = 0;
            for (int j = 0; j < 8; j++) {
                int rr = rows[gid * 8 + j];
                if (rr < 8) cl |= 1 << rr; else ch |= 1 << (rr - 8);
            }
            int j = __popc(cl);
            g_invmap[c_OFF2[j] + s_rank[cl] * c_NJ[j] + s_rank[ch]] = gid;
        }
    }
    // zero sums, out = bias (one block)
    if (blockIdx.x == 0 && side == 0 && b == 0) {
        if (t < BATCH) g_sum[t] = 0.f;
        for (int q = t; q < BATCH * OUTD; q += 256) out[q] = bias[q & 127];
    }
}

// ============ kernel 2: uniform-tile class GEMMs + fused epilogue ============
// grid: (NTILE, BATCH), 256 threads; block: 32x32 outputs x K=128
__global__ __launch_bounds__(256) void k_classes() {
    __shared__ __align__(16) float4 sh4[2][KC][16];
    __shared__ float red[8];
    int t = threadIdx.x;
    int tile = blockIdx.x, b = blockIdx.y;
    int j  = c_TJ[tile];
    int a0 = c_TA[tile], b0 = c_TB[tile];
    int n  = c_NJ[j];
    int base4L = (c_POFF[j] + a0) >> 1;
    int base4H = (c_POFF[8 - j] + b0) >> 1;
    int ty = t >> 4, tx = t & 15;

    const float4* Lg4 = (const float4*)&g_PT[b][0][0][0];
    const float4* Hg4 = (const float4*)&g_PT[b][1][0][0];

    // stage decode: thread loads one float4 per side per stage
    int kkl = t >> 4, c4 = t & 15;

    float aR00 = 0, aI00 = 0, aR01 = 0, aI01 = 0;
    float aR10 = 0, aI10 = 0, aR11 = 0, aI11 = 0;

    float4 pfL = Lg4[(size_t)kkl * PW4 + base4L + c4];
    float4 pfH = Hg4[(size_t)kkl * PW4 + base4H + c4];

#pragma unroll 1
    for (int st = 0; st < NDEL; st += KC) {
        sh4[0][kkl][c4] = pfL;
        sh4[1][kkl][c4] = pfH;
        __syncthreads();
        if (st + KC < NDEL) {
            pfL = Lg4[(size_t)(st + KC + kkl) * PW4 + base4L + c4];
            pfH = Hg4[(size_t)(st + KC + kkl) * PW4 + base4H + c4];
        }
#pragma unroll
        for (int kk = 0; kk < KC; kk++) {
            float4 Lv = sh4[0][kk][ty];
            float4 Hv = sh4[1][kk][tx];
            aR00 += Lv.x * Hv.x - Lv.y * Hv.y;  aI00 += Lv.x * Hv.y + Lv.y * Hv.x;
            aR01 += Lv.x * Hv.z - Lv.y * Hv.w;  aI01 += Lv.x * Hv.w + Lv.y * Hv.z;
            aR10 += Lv.z * Hv.x - Lv.w * Hv.y;  aI10 += Lv.z * Hv.y + Lv.w * Hv.x;
            aR11 += Lv.z * Hv.z - Lv.w * Hv.w;  aI11 += Lv.z * Hv.w + Lv.w * Hv.z;
        }
        __syncthreads();
    }
    // epilogue: square, scatter via invmap, batch-sum
    float local = 0.f;
    int off2 = c_OFF2[j];
    float pr[4] = { aR00 * aR00 + aI00 * aI00, aR01 * aR01 + aI01 * aI01,
                    aR10 * aR10 + aI10 * aI10, aR11 * aR11 + aI11 * aI11 };
    int aa[2] = { a0 + ty * 2, a0 + ty * 2 + 1 };
    int bb[2] = { b0 + tx * 2, b0 + tx * 2 + 1 };
#pragma unroll
    for (int i = 0; i < 2; i++)
#pragma unroll
        for (int i2 = 0; i2 < 2; i2++) {
            if (aa[i] < n && bb[i2] < n) {
                float p = pr[i * 2 + i2];
                g_praw[b][g_invmap[off2 + aa[i] * n + bb[i2]]] = p;
                local += p;
            }
        }
    for (int off = 16; off; off >>= 1)
        local += __shfl_down_sync(0xffffffffu, local, off);
    if ((t & 31) == 0) red[t >> 5] = local;
    __syncthreads();
    if (t == 0) {
        float v = 0.f;
#pragma unroll
        for (int q = 0; q < 8; q++) v += red[q];
        atomicAdd(&g_sum[b], v);
    }
}

// ============ kernel 3: out += (praw/sum) @ weight ============
#define KCH 64
__global__ __launch_bounds__(256) void k_gemm(const float* __restrict__ weight,
                                              float* __restrict__ out) {
    __shared__ float pr[BATCH][KCH];
    __shared__ float red[BATCH][OUTD];
    __shared__ float s_inv[BATCH];
    int t = threadIdx.x;
    int n = t & 127;
    int kp = t >> 7;                      // 0..1
    int k0 = blockIdx.x * KCH;
    int klen = NST - k0; if (klen > KCH) klen = KCH;

    if (t < BATCH) s_inv[t] = 1.f / g_sum[t];
    for (int idx = t; idx < BATCH * KCH; idx += 256) {
        int bb = idx >> 6, kk = idx & 63;
        pr[bb][kk] = (kk < klen) ? g_praw[bb][k0 + kk] : 0.f;
    }
    __syncthreads();
    float acc[BATCH];
#pragma unroll
    for (int bb = 0; bb < BATCH; bb++) acc[bb] = 0.f;
    for (int kk = kp; kk < klen; kk += 2) {
        float wv = weight[(size_t)(k0 + kk) * OUTD + n];
#pragma unroll
        for (int bb = 0; bb < BATCH; bb++) acc[bb] += wv * pr[bb][kk];
    }
    if (kp == 1) {
#pragma unroll
        for (int bb = 0; bb < BATCH; bb++) red[bb][n] = acc[bb];
    }
    __syncthreads();
    if (kp == 0) {
#pragma unroll
        for (int bb = 0; bb < BATCH; bb++)
            atomicAdd(&out[bb * OUTD + n], (acc[bb] + red[bb][n]) * s_inv[bb]);
    }
}

// ============ launch ============
extern "C" void kernel_launch(void* const* d_in, const int* in_sizes, int n_in,
                              void* d_out, int out_size) {
    const float* x   = (const float*)d_in[0];
    const float* th1 = (const float*)d_in[1];
    const float* th2 = (const float*)d_in[2];
    const float* mr  = (const float*)d_in[3];
    const float* mi  = (const float*)d_in[4];
    const float* w   = (const float*)d_in[5];
    const float* bia = (const float*)d_in[6];
    const int* rows  = (const int*)d_in[7];
    float* out = (float*)d_out;

    k_tables<<<dim3(NDEL / CS2, 2, BATCH), 256>>>(x, th1, th2, mr, mi, rows, bia, out);
    k_classes<<<dim3(NTILE, BATCH), 256>>>();
    k_gemm<<<(NST + KCH - 1) / KCH, 256>>>(w, out);
}

// round 8
// speedup vs baseline: 1.4212x; 1.4212x over previous
#include <cuda_runtime.h>

#define BATCH 8
#define MODES 16
#define NPH   8
#define NST   12870
#define OUTD  128
#define NDEL  128          // Glynn: 2^(n-1) terms
#define CSG   8            // deltas per glynn block
#define KC    16           // K stage depth in class GEMM
#define NTILE 23
#define PW    416          // padded table width (32-aligned class windows)
#define PW4   (PW / 2)

__constant__ int c_NJ[9]   = {1, 8, 28, 56, 70, 56, 28, 8, 1};
__constant__ int c_POFF[9] = {0, 32, 64, 96, 160, 256, 320, 352, 384};
__constant__ int c_OFF2[9] = {0, 1, 65, 849, 3985, 8885, 12021, 12805, 12869};
__constant__ int c_TJ[NTILE]  = {4,4,4,4,4,4,4,4,4, 3,3,3,3, 5,5,5,5, 2,6,1,7,0,8};
__constant__ int c_TA[NTILE]  = {0,0,0,32,32,32,64,64,64, 0,0,32,32, 0,0,32,32, 0,0,0,0,0,0};
__constant__ int c_TB[NTILE]  = {0,32,64,0,32,64,0,32,64, 0,32,0,32, 0,32,0,32, 0,0,0,0,0,0};

// ---------------- device scratch ----------------
__device__ __align__(16) float2 g_PT[BATCH][2][NDEL][PW];   // 6.8MB padded tables
__device__ __align__(16) float2 g_uin[BATCH][MODES][NPH];   // 8KB
__device__ int    g_posmap[PW];
__device__ int    g_rank[256];
__device__ int    g_invmap[NST];
__device__ float  g_praw[BATCH][NST];
__device__ float  g_sum[BATCH];

// ============ kernel 1: one-block prep: maps, A/B, uin, out=bias ============
__global__ __launch_bounds__(256) void k_prep(const float* __restrict__ x,
                                              const float* __restrict__ th1,
                                              const float* __restrict__ th2,
                                              const float* __restrict__ mr,
                                              const float* __restrict__ mi,
                                              const float* __restrict__ bias,
                                              float* __restrict__ out) {
    __shared__ float2 e1[16], e2[16], ex[BATCH][16];
    __shared__ float2 A[16][16], Bm[16][16];
    int t = threadIdx.x;

    if (t < 16) {
        float s, c;
        sincosf(th1[t], &s, &c); e1[t] = make_float2(c, s);
        sincosf(th2[t], &s, &c); e2[t] = make_float2(c, s);
    }
    if (t < BATCH * 16) {
        int b = t >> 4, m = t & 15;
        float s, c; sincosf(x[b * 16 + m], &s, &c);
        ex[b][m] = make_float2(c, s);
    }
    // posmap init + rank
    if (t < PW - 256) g_posmap[256 + t] = -1;
    {
        int c = t, pc = __popc(c), r = 0;
        for (int cp = 0; cp < c; cp++) r += (__popc(cp) == pc) ? 1 : 0;
        g_rank[c] = r;
        // overwrite all valid positions below; first clear own slot range
        g_posmap[c] = -1;
    }
    __syncthreads();
    {
        int c = t;
        g_posmap[c_POFF[__popc(c)] + g_rank[c]] = c;
    }
    __syncthreads();
    // A = M1 diag(e1) M0 ; B = M3 diag(e2) M2
    {
        int i = t >> 4, j = t & 15;
        float ar = 0, ai = 0, br = 0, bi = 0;
        for (int m = 0; m < 16; m++) {
            float m1r = mr[256 + i * 16 + m], m1i = mi[256 + i * 16 + m];
            float m0r = mr[m * 16 + j],       m0i = mi[m * 16 + j];
            float tr = e1[m].x * m0r - e1[m].y * m0i;
            float ti = e1[m].x * m0i + e1[m].y * m0r;
            ar += m1r * tr - m1i * ti;
            ai += m1r * ti + m1i * tr;
            float m3r = mr[3 * 256 + i * 16 + m], m3i = mi[3 * 256 + i * 16 + m];
            float m2r = mr[2 * 256 + m * 16 + j], m2i = mi[2 * 256 + m * 16 + j];
            float ur = e2[m].x * m2r - e2[m].y * m2i;
            float ui = e2[m].x * m2i + e2[m].y * m2r;
            br += m3r * ur - m3i * ui;
            bi += m3r * ui + m3i * ur;
        }
        A[i][j]  = make_float2(ar, ai);
        Bm[i][j] = make_float2(br, bi);
    }
    __syncthreads();
    // uin[b][p][n] for all b, p in 0..15, n<8 : 1024 entries, 4 per thread
#pragma unroll
    for (int q = 0; q < 4; q++) {
        int idx = t + q * 256;
        int b = idx >> 7, p = (idx >> 3) & 15, n = idx & 7;
        float ur = 0, ui = 0;
        for (int m = 0; m < 16; m++) {
            float tr = ex[b][m].x * A[m][n].x - ex[b][m].y * A[m][n].y;
            float ti = ex[b][m].x * A[m][n].y + ex[b][m].y * A[m][n].x;
            ur += Bm[p][m].x * tr - Bm[p][m].y * ti;
            ui += Bm[p][m].x * ti + Bm[p][m].y * tr;
        }
        g_uin[b][p][n] = make_float2(ur, ui);
    }
    if (t < BATCH) g_sum[t] = 0.f;
    for (int q = t; q < BATCH * OUTD; q += 256) out[q] = bias[q & 127];
}

// ============ kernel 2: Glynn tables (rowsums + subset-product DP + write) ==
// grid: (NDEL/CSG=16, 2, 8) = 256 blocks, 256 threads
__global__ __launch_bounds__(256) void k_glynn(const int* __restrict__ rows) {
    __shared__ float2 uin[8][8];
    __shared__ float2 vs[CSG][8];
    __shared__ float2 P[256][CSG + 1];
    __shared__ int pm[PW];

    int t = threadIdx.x;
    int d0 = blockIdx.x * CSG;
    int side = blockIdx.y, b = blockIdx.z;

    // loads
    if (t < 64) {
        int r = t >> 3, n = t & 7;
        uin[r][n] = g_uin[b][side * 8 + r][n];
    }
    for (int q = t; q < PW; q += 256) pm[q] = g_posmap[q];
    __syncthreads();
    // Glynn row sums; P[0] = sign*scale (folded into all products)
    if (t < CSG * 8) {
        int sl = t >> 3, r = t & 7, d = d0 + sl;
        float vr = uin[r][0].x, vi = uin[r][0].y;
#pragma unroll
        for (int k = 1; k < 8; k++) {
            if ((d >> (k - 1)) & 1) { vr -= uin[r][k].x; vi -= uin[r][k].y; }
            else                    { vr += uin[r][k].x; vi += uin[r][k].y; }
        }
        vs[sl][r] = make_float2(vr, vi);
    }
    if (t < CSG) {
        float f = 1.f;
        if (side == 1) f = ((__popc(d0 + t) & 1) ? -0.0078125f : 0.0078125f);
        P[0][t] = make_float2(f, 0.f);
    }
    __syncthreads();
    // subset-product DP
#pragma unroll
    for (int r = 0; r < 8; r++) {
        int cnt = (1 << r) * CSG;
        for (int idx = t; idx < cnt; idx += 256) {
            int cprev = idx >> 3, sl = idx & 7;
            float2 p = P[cprev][sl], v = vs[sl][r];
            P[cprev | (1 << r)][sl] =
                make_float2(p.x * v.x - p.y * v.y, p.x * v.y + p.y * v.x);
        }
        __syncthreads();
    }
    // coalesced padded write
#pragma unroll
    for (int sl = 0; sl < CSG; sl++) {
        int d = d0 + sl;
        for (int pos = t; pos < PW; pos += 256) {
            int mask = pm[pos];
            float2 p = (mask >= 0) ? P[mask][sl] : make_float2(0.f, 0.f);
            g_PT[b][side][d][pos] = p;
        }
    }
    // inverse state map (side-0: 128 blocks x 256 = 32768 >= NST)
    if (side == 0) {
        int gid = (blockIdx.x + 16 * blockIdx.z) * 256 + t;
        if (gid < NST) {
            int cl = 0, ch = 0;
#pragma unroll
            for (int j = 0; j < 8; j++) {
                int rr = rows[gid * 8 + j];
                if (rr < 8) cl |= 1 << rr; else ch |= 1 << (rr - 8);
            }
            int j = __popc(cl);
            g_invmap[c_OFF2[j] + g_rank[cl] * c_NJ[j] + g_rank[ch]] = gid;
        }
    }
}

// ============ kernel 3: uniform-tile class GEMMs + fused epilogue ============
__global__ __launch_bounds__(256) void k_classes() {
    __shared__ __align__(16) float4 sh4[2][KC][16];
    __shared__ float red[8];
    int t = threadIdx.x;
    int tile = blockIdx.x, b = blockIdx.y;
    int j  = c_TJ[tile];
    int a0 = c_TA[tile], b0 = c_TB[tile];
    int n  = c_NJ[j];
    int base4L = (c_POFF[j] + a0) >> 1;
    int base4H = (c_POFF[8 - j] + b0) >> 1;
    int ty = t >> 4, tx = t & 15;

    const float4* Lg4 = (const float4*)&g_PT[b][0][0][0];
    const float4* Hg4 = (const float4*)&g_PT[b][1][0][0];

    int kkl = t >> 4, c4 = t & 15;

    float aR00 = 0, aI00 = 0, aR01 = 0, aI01 = 0;
    float aR10 = 0, aI10 = 0, aR11 = 0, aI11 = 0;

    float4 pfL = Lg4[(size_t)kkl * PW4 + base4L + c4];
    float4 pfH = Hg4[(size_t)kkl * PW4 + base4H + c4];

#pragma unroll 1
    for (int st = 0; st < NDEL; st += KC) {
        sh4[0][kkl][c4] = pfL;
        sh4[1][kkl][c4] = pfH;
        __syncthreads();
        if (st + KC < NDEL) {
            pfL = Lg4[(size_t)(st + KC + kkl) * PW4 + base4L + c4];
            pfH = Hg4[(size_t)(st + KC + kkl) * PW4 + base4H + c4];
        }
#pragma unroll
        for (int kk = 0; kk < KC; kk++) {
            float4 Lv = sh4[0][kk][ty];
            float4 Hv = sh4[1][kk][tx];
            aR00 += Lv.x * Hv.x - Lv.y * Hv.y;  aI00 += Lv.x * Hv.y + Lv.y * Hv.x;
            aR01 += Lv.x * Hv.z - Lv.y * Hv.w;  aI01 += Lv.x * Hv.w + Lv.y * Hv.z;
            aR10 += Lv.z * Hv.x - Lv.w * Hv.y;  aI10 += Lv.z * Hv.y + Lv.w * Hv.x;
            aR11 += Lv.z * Hv.z - Lv.w * Hv.w;  aI11 += Lv.z * Hv.w + Lv.w * Hv.z;
        }
        __syncthreads();
    }
    float local = 0.f;
    int off2 = c_OFF2[j];
    float pr[4] = { aR00 * aR00 + aI00 * aI00, aR01 * aR01 + aI01 * aI01,
                    aR10 * aR10 + aI10 * aI10, aR11 * aR11 + aI11 * aI11 };
    int aa[2] = { a0 + ty * 2, a0 + ty * 2 + 1 };
    int bb[2] = { b0 + tx * 2, b0 + tx * 2 + 1 };
#pragma unroll
    for (int i = 0; i < 2; i++)
#pragma unroll
        for (int i2 = 0; i2 < 2; i2++) {
            if (aa[i] < n && bb[i2] < n) {
                float p = pr[i * 2 + i2];
                g_praw[b][g_invmap[off2 + aa[i] * n + bb[i2]]] = p;
                local += p;
            }
        }
    for (int off = 16; off; off >>= 1)
        local += __shfl_down_sync(0xffffffffu, local, off);
    if ((t & 31) == 0) red[t >> 5] = local;
    __syncthreads();
    if (t == 0) {
        float v = 0.f;
#pragma unroll
        for (int q = 0; q < 8; q++) v += red[q];
        atomicAdd(&g_sum[b], v);
    }
}

// ============ kernel 4: out += (praw/sum) @ weight ============
#define KCH 64
__global__ __launch_bounds__(256) void k_gemm(const float* __restrict__ weight,
                                              float* __restrict__ out) {
    __shared__ float pr[BATCH][KCH];
    __shared__ float red[BATCH][OUTD];
    __shared__ float s_inv[BATCH];
    int t = threadIdx.x;
    int n = t & 127;
    int kp = t >> 7;
    int k0 = blockIdx.x * KCH;
    int klen = NST - k0; if (klen > KCH) klen = KCH;

    if (t < BATCH) s_inv[t] = 1.f / g_sum[t];
    for (int idx = t; idx < BATCH * KCH; idx += 256) {
        int bb = idx >> 6, kk = idx & 63;
        pr[bb][kk] = (kk < klen) ? g_praw[bb][k0 + kk] : 0.f;
    }
    __syncthreads();
    float acc[BATCH];
#pragma unroll
    for (int bb = 0; bb < BATCH; bb++) acc[bb] = 0.f;
    for (int kk = kp; kk < klen; kk += 2) {
        float wv = weight[(size_t)(k0 + kk) * OUTD + n];
#pragma unroll
        for (int bb = 0; bb < BATCH; bb++) acc[bb] += wv * pr[bb][kk];
    }
    if (kp == 1) {
#pragma unroll
        for (int bb = 0; bb < BATCH; bb++) red[bb][n] = acc[bb];
    }
    __syncthreads();
    if (kp == 0) {
#pragma unroll
        for (int bb = 0; bb < BATCH; bb++)
            atomicAdd(&out[bb * OUTD + n], (acc[bb] + red[bb][n]) * s_inv[bb]);
    }
}

// ============ launch ============
extern "C" void kernel_launch(void* const* d_in, const int* in_sizes, int n_in,
                              void* d_out, int out_size) {
    const float* x   = (const float*)d_in[0];
    const float* th1 = (const float*)d_in[1];
    const float* th2 = (const float*)d_in[2];
    const float* mr  = (const float*)d_in[3];
    const float* mi  = (const float*)d_in[4];
    const float* w   = (const float*)d_in[5];
    const float* bia = (const float*)d_in[6];
    const int* rows  = (const int*)d_in[7];
    float* out = (float*)d_out;

    k_prep<<<1, 256>>>(x, th1, th2, mr, mi, bia, out);
    k_glynn<<<dim3(NDEL / CSG, 2, BATCH), 256>>>(rows);
    k_classes<<<dim3(NTILE, BATCH), 256>>>();
    k_gemm<<<(NST + KCH - 1) / KCH, 256>>>(w, out);
}